// round 3
// baseline (speedup 1.0000x reference)
#include <cuda_runtime.h>
#include <cstdint>

// ---------------- problem constants (fixed shapes) ----------------
#define NNODES 10000
#define NEDGES 80000
#define BF     48          // B*S = 4*12
#define DD     32
#define NH     4
#define NK     3
#define NHK    12          // H*K
#define NC     24          // 12 src scores + 12 dst scores
#define NROWS  (BF * NNODES)   // 480000
#define NTASKS (NNODES * (BF / 2))   // 240000 warp tasks

// ---------------- device scratch (static, allocation-free) ----------------
__device__ float g_S[(size_t)NROWS * NC];        // 46 MB : per-row 24 scores
__device__ float g_wv[NC * DD];                  // 24 x 32 projection vectors
__device__ int   g_counts[NNODES];
__device__ int   g_off[NNODES + 1];
__device__ int   g_fill[NNODES];
__device__ int   g_eid[NEDGES];

// ---------------- packed f32x2 helpers (Blackwell) ----------------
__device__ __forceinline__ unsigned long long pk2(float x, float y) {
    unsigned long long r;
    asm("mov.b64 %0, {%1, %2};" : "=l"(r) : "f"(x), "f"(y));
    return r;
}
__device__ __forceinline__ void ffma2(unsigned long long& acc,
                                      unsigned long long a, unsigned long long b) {
    asm("fma.rn.f32x2 %0, %1, %2, %0;" : "+l"(acc) : "l"(a), "l"(b));
}
__device__ __forceinline__ float2 unpk2(unsigned long long v) {
    float lo, hi;
    asm("mov.b64 {%0, %1}, %2;" : "=f"(lo), "=f"(hi) : "l"(v));
    return make_float2(lo, hi);
}

// ---------------- K1: wv[c][i] = sum_j W[h,k,i,j] * a_{src|dst}[h,j] ----------------
__global__ void k_wvec(const float* __restrict__ W,
                       const float* __restrict__ a_src,
                       const float* __restrict__ a_dst) {
    int t = threadIdx.x;
    if (t >= NC * DD) return;
    int c  = t >> 5;            // 0..23
    int i  = t & 31;
    int hk = (c < NHK) ? c : c - NHK;
    const float* av  = (c < NHK) ? (a_src + (hk / NK) * DD) : (a_dst + (hk / NK) * DD);
    const float* wr  = W + ((size_t)hk * DD + i) * DD;
    float s = 0.f;
#pragma unroll
    for (int j = 0; j < DD; j++) s = fmaf(wr[j], av[j], s);
    g_wv[c * DD + i] = s;
}

// ---------------- K2: S[row][c] = x[row] . wv[c]  (row = b*N+n) ----------------
__global__ void __launch_bounds__(256) k_scores(const float* __restrict__ x) {
    __shared__ float wv[NC * DD];
    for (int i = threadIdx.x; i < NC * DD; i += blockDim.x) wv[i] = g_wv[i];
    __syncthreads();
    int row = blockIdx.x * blockDim.x + threadIdx.x;
    if (row >= NROWS) return;
    const float4* xr = (const float4*)(x + (size_t)row * DD);
    float xv[DD];
#pragma unroll
    for (int q = 0; q < 8; q++) {
        float4 v = xr[q];
        xv[4 * q + 0] = v.x; xv[4 * q + 1] = v.y; xv[4 * q + 2] = v.z; xv[4 * q + 3] = v.w;
    }
    float* srow = g_S + (size_t)row * NC;
#pragma unroll
    for (int c = 0; c < NC; c++) {
        float s = 0.f;
#pragma unroll
        for (int i = 0; i < DD; i++) s = fmaf(xv[i], wv[c * DD + i], s);
        srow[c] = s;
    }
}

// ---------------- CSR build ----------------
__global__ void k_zero() {
    int t = blockIdx.x * blockDim.x + threadIdx.x;
    if (t < NNODES) { g_counts[t] = 0; g_fill[t] = 0; }
}
__global__ void k_hist(const int* __restrict__ dst) {
    int e = blockIdx.x * blockDim.x + threadIdx.x;
    if (e < NEDGES) atomicAdd(&g_counts[dst[e]], 1);
}
__global__ void k_scan() {   // 1 block, 1024 threads
    __shared__ int buf[1024];
    int tid = threadIdx.x;
    int carry = 0;
    for (int base = 0; base < NNODES; base += 1024) {
        int idx = base + tid;
        int v = (idx < NNODES) ? g_counts[idx] : 0;
        buf[tid] = v;
        __syncthreads();
        int incl = v;
#pragma unroll
        for (int d = 1; d < 1024; d <<= 1) {
            int t2 = (tid >= d) ? buf[tid - d] : 0;
            __syncthreads();
            incl += t2;
            buf[tid] = incl;
            __syncthreads();
        }
        if (idx < NNODES) g_off[idx] = carry + incl - v;
        carry += buf[1023];
        __syncthreads();
    }
    if (tid == 0) g_off[NNODES] = carry;
}
__global__ void k_scatter(const int* __restrict__ dst) {
    int e = blockIdx.x * blockDim.x + threadIdx.x;
    if (e < NEDGES) {
        int d = dst[e];
        int pos = g_off[d] + atomicAdd(&g_fill[d], 1);
        g_eid[pos] = e;
    }
}

// ---------------- K4: fused softmax + aggregation + GEMM + epilogue --------------
// Per warp task (n, bp): batch rows b0=2*bp, b0+1.
//   pass A: online softmax stats per (hk, b) on lanes 0..23
//   pass B: agg[hk] (float2 of dims 2qi, 2qi+1 for b = b0 + lane/16) via alpha shuffles
//   pass C: out = relu( (Sum_hk agg_hk @ W[hk]) / H + inputs ), W transposed in smem,
//           packed fma.rn.f32x2 along the K dimension.
__global__ void __launch_bounds__(256) k_fused(const float* __restrict__ x,
                                               const int*   __restrict__ src,
                                               const float* __restrict__ sup,
                                               const float* __restrict__ W,
                                               const float* __restrict__ inp,
                                               float*       __restrict__ out) {
    // Wt[hk][q][d] = (W[hk][2q][d], W[hk][2q+1][d])   : 12*16*32 float2 = 48KB
    __shared__ float2 Wt[NHK * 16 * DD];
    for (int t = threadIdx.x; t < NHK * 16 * DD; t += 256) {
        int hk = t >> 9;
        int q  = (t >> 5) & 15;
        int d  = t & 31;
        const float* wb = W + (size_t)hk * (DD * DD);
        Wt[t] = make_float2(wb[(2 * q) * DD + d], wb[(2 * q + 1) * DD + d]);
    }
    __syncthreads();

    int lane   = threadIdx.x & 31;
    int warp0  = (blockIdx.x * blockDim.x + threadIdx.x) >> 5;
    int nwarps = (gridDim.x * blockDim.x) >> 5;

    int  hk    = lane % NHK;
    bool actA  = lane < 2 * NHK;
    int  kk    = hk % NK;
    int  qi    = lane & 15;
    int  bhalf = lane >> 4;
    int  sbase = bhalf * NHK;           // alpha shuffle source base: 0 or 12

    for (int task = warp0; task < NTASKS; task += nwarps) {
        int n  = task % NNODES;
        int bp = task / NNODES;
        int b0 = bp * 2;
        int p0 = g_off[n], p1 = g_off[n + 1];

        int bA = b0 + ((lane < NHK) ? 0 : 1);
        const float* Sb = g_S + (size_t)bA * NNODES * NC + hk;

        // ---- pass A: online softmax (max & denom) per (hk, b) on lanes 0..23 ----
        float m = -1e30f, den = 0.f, sd = 0.f;
        if (actA) sd = Sb[(size_t)n * NC + NHK];
        for (int p = p0; p < p1; p++) {
            int e = g_eid[p];
            int s = __ldg(&src[e]);
            if (actA) {
                float l = Sb[(size_t)s * NC] + sd;
                l = (l > 0.f) ? l : 0.2f * l;
                float nm = fmaxf(m, l);
                den = den * __expf(m - nm) + __expf(l - nm);
                m = nm;
            }
        }
        float invden = 1.f / (den + 1e-9f);

        // ---- pass B: alpha * support_w weighted aggregation of x[src] ----
        int bB = b0 + bhalf;
        const float* xb = x + ((size_t)bB * NNODES) * DD + 2 * qi;
        float2 agg[NHK];
#pragma unroll
        for (int j = 0; j < NHK; j++) agg[j] = make_float2(0.f, 0.f);

        // prefetch first edge of this run (already L1-hot from pass A)
        int e_nx = (p0 < p1) ? g_eid[p0] : 0;
        int s_nx = (p0 < p1) ? __ldg(&src[e_nx]) : 0;
        for (int p = p0; p < p1; p++) {
            int e = e_nx, s = s_nx;
            if (p + 1 < p1) {
                e_nx = g_eid[p + 1];
                s_nx = __ldg(&src[e_nx]);
            }
            float a = 0.f;
            if (actA) {
                float l = Sb[(size_t)s * NC] + sd;
                l = (l > 0.f) ? l : 0.2f * l;
                a = __expf(l - m) * invden * __ldg(&sup[kk * NEDGES + e]);
            }
            float2 xv = *(const float2*)(xb + (size_t)s * DD);
#pragma unroll
            for (int j = 0; j < NHK; j++) {
                float aj = __shfl_sync(0xffffffffu, a, sbase + j);
                agg[j].x = fmaf(aj, xv.x, agg[j].x);
                agg[j].y = fmaf(aj, xv.y, agg[j].y);
            }
        }

        // ---- pass C: tile-GEMM with packed f32x2, W in smem ----
        // lane owns output dims dA=qi and dB=qi+16 for batch row bB.
        unsigned long long accA = 0ull, accB = 0ull;   // (0.0f, 0.0f)
        int srcBase = bhalf << 4;
#pragma unroll 1
        for (int j = 0; j < NHK; j++) {
            const unsigned long long* wrow =
                (const unsigned long long*)(Wt + j * (16 * DD));
            float ax = agg[j].x, ay = agg[j].y;
#pragma unroll
            for (int q = 0; q < 16; q++) {
                float vx = __shfl_sync(0xffffffffu, ax, srcBase | q);
                float vy = __shfl_sync(0xffffffffu, ay, srcBase | q);
                unsigned long long av = pk2(vx, vy);
                ffma2(accA, av, wrow[q * DD + qi]);
                ffma2(accB, av, wrow[q * DD + qi + 16]);
            }
        }
        float2 ra = unpk2(accA), rb = unpk2(accB);
        float oA = (ra.x + ra.y) * 0.25f;
        float oB = (rb.x + rb.y) * 0.25f;
        size_t rowoff = ((size_t)bB * NNODES + n) * DD;
        out[rowoff + qi]      = fmaxf(oA + inp[rowoff + qi], 0.f);
        out[rowoff + qi + 16] = fmaxf(oB + inp[rowoff + qi + 16], 0.f);
    }
}

// ---------------- launch ----------------
extern "C" void kernel_launch(void* const* d_in, const int* in_sizes, int n_in,
                              void* d_out, int out_size) {
    const float* x     = (const float*)d_in[0];   // [48,10000,32]
    const int*   src   = (const int*)  d_in[1];   // [E]
    const int*   dst   = (const int*)  d_in[2];   // [E]
    const float* sup   = (const float*)d_in[3];   // [3,E]
    const float* W     = (const float*)d_in[4];   // [4,3,32,32]
    const float* a_s   = (const float*)d_in[5];   // [4,32]
    const float* a_d   = (const float*)d_in[6];   // [4,32]
    float*       out   = (float*)d_out;

    k_wvec<<<1, NC * DD>>>(W, a_s, a_d);
    k_scores<<<(NROWS + 255) / 256, 256>>>(x);
    k_zero<<<(NNODES + 255) / 256, 256>>>();
    k_hist<<<(NEDGES + 255) / 256, 256>>>(dst);
    k_scan<<<1, 1024>>>();
    k_scatter<<<(NEDGES + 255) / 256, 256>>>(dst);
    k_fused<<<592, 256>>>(x, src, sup, W, x, out);
}